// round 6
// baseline (speedup 1.0000x reference)
#include <cuda_runtime.h>
#include <cuda_bf16.h>

#define NN      65536
#define NE      1048576
#define NG      64
#define NPG     1024
#define CF      8
#define PAD     9
#define RSTRIDE 64      // fixed slots per node (in-degree ~Poisson(16), P(>60) ~ 1e-18)

typedef unsigned long long ull;

__device__ int   g_deg[NN];                    // out-degree (for dis)
__device__ int   g_cnt[NN];                    // in-degree  (row length)
__device__ int   g_cur[NN];
__device__ int2  g_edges[(size_t)NN * RSTRIDE]; // zero-init; pad slots never written
__device__ float g_tx[640ull * NN];
__device__ float g_ha[(size_t)NN * 64];
__device__ float g_hb[(size_t)NN * 64];

__device__ __forceinline__ ull pack2(float x, float y) {
    ull r; asm("mov.b64 %0, {%1, %2};" : "=l"(r) : "f"(x), "f"(y)); return r;
}
__device__ __forceinline__ void ffma2(ull& d, ull a, ull b) {
    asm("fma.rn.f32x2 %0, %1, %2, %0;" : "+l"(d) : "l"(a), "l"(b));
}
__device__ __forceinline__ void unpack2(ull v, float& x, float& y) {
    asm("mov.b64 {%0, %1}, %2;" : "=f"(x), "=f"(y) : "l"(v));
}

// ---------------- prep (3 kernels) ----------------
__global__ void zero_kernel() {
    int i = blockIdx.x * blockDim.x + threadIdx.x;
    if (i < NN) { g_deg[i] = 0; g_cnt[i] = 0; g_cur[i] = 0; }
}

__global__ void deg_kernel(const int* __restrict__ ei) {
    int e = blockIdx.x * blockDim.x + threadIdx.x;
    if (e >= NE) return;
    int s = ei[e], d = ei[NE + e];
    if (s != d) { atomicAdd(&g_deg[s], 1); atomicAdd(&g_cnt[d], 1); }
}

__global__ void fill_kernel(const int* __restrict__ ei,
                            const float* __restrict__ lam) {
    int e = blockIdx.x * blockDim.x + threadIdx.x;
    if (e >= NE) return;
    int s = ei[e], d = ei[NE + e];
    if (s == d) return;
    int od = g_deg[d];
    float dd = (od > 0) ? rsqrtf((float)od) : 0.0f;     // dis[dst] uses out-degree of dst
    float w = -2.0f * rsqrtf((float)g_deg[s]) * dd / lam[s >> 10];
    int slot = atomicAdd(&g_cur[d], 1);
    g_edges[(size_t)d * RSTRIDE + slot] = make_int2(s & (NPG - 1), __float_as_int(w));
}

// ---------------- Chebyshev recurrence ----------------
// CTA = (8-feature chunk, graph). 1024 threads, 2 CTAs/SM.
// Warp owns 32 nodes sequentially; per node, 4 parallel edge streams
// (lane sub-groups of 8; fl = lane&7 is the feature).
template<int F>
__global__ void __launch_bounds__(1024, 2)
spmv_kernel(const float* __restrict__ hin, const float* __restrict__ lam,
            float* __restrict__ txout) {
    extern __shared__ float sm[];
    float* buf0 = sm;
    float* buf1 = sm + NPG * PAD;

    const int g = blockIdx.y, cb = blockIdx.x * CF, t = threadIdx.x;
    const int gbase = g * NPG;
    const float diag = 2.0f / lam[g] - 1.0f;

    const float* hp = hin + (size_t)gbase * F + cb;
    #pragma unroll
    for (int r = 0; r < CF; r++) {
        int i = r * 1024 + t;
        buf0[(i >> 3) * PAD + (i & 7)] = hp[(i >> 3) * F + (i & 7)];
    }
    __syncthreads();

    #pragma unroll
    for (int f = 0; f < CF; f++)
        txout[(size_t)(cb + f) * NN + gbase + t] = buf0[t * PAD + f];

    const int lane = t & 31, warp = t >> 5;
    const int fl = lane & 7, sub = lane >> 3;   // 4 edge streams per node
    float* cur = buf0; float* oth = buf1;

    for (int k = 1; k < 5; k++) {
        #pragma unroll 1
        for (int p = 0; p < 32; p++) {
            int dloc = warp * 32 + p;
            int node = gbase + dloc;
            int deg  = g_cnt[node];
            int quads = (deg + 3) >> 2;
            const int2* base = g_edges + (size_t)node * RSTRIDE + sub;
            float acc = 0.0f;
            int i = 0;
            for (; i + 2 <= quads; i += 2) {
                int2 e0 = base[4 * i];
                int2 e1 = base[4 * i + 4];
                acc += __int_as_float(e0.y) * cur[e0.x * PAD + fl];
                acc += __int_as_float(e1.y) * cur[e1.x * PAD + fl];
            }
            if (i < quads) {
                int2 e0 = base[4 * i];
                acc += __int_as_float(e0.y) * cur[e0.x * PAD + fl];
            }
            acc += __shfl_xor_sync(0xffffffffu, acc, 8);
            acc += __shfl_xor_sync(0xffffffffu, acc, 16);
            if (sub == 0) {
                int idx = dloc * PAD + fl;
                float lh = acc + diag * cur[idx];
                oth[idx] = (k == 1) ? lh : 2.0f * lh - oth[idx];
            }
        }
        __syncthreads();
        #pragma unroll
        for (int f = 0; f < CF; f++)
            txout[(size_t)(k * F + cb + f) * NN + gbase + t] = oth[t * PAD + f];
        float* tmp = cur; cur = oth; oth = tmp;
        __syncthreads();
    }
}

// ---------------- GEMM: out = relu(A^T W + b), A:[K][NN], W:[K][N] ----------------
template<int K, int N, int MT>
__global__ void __launch_bounds__(256)
gemm_kernel(const float* __restrict__ A, const float* __restrict__ W,
            const float* __restrict__ bias, float* __restrict__ out) {
    constexpr int NJG = N / 8;
    constexpr int MG  = MT / 8;
    static_assert(MG * NJG == 256, "cfg");
    __shared__ __align__(16) float As[16 * MT];
    __shared__ __align__(16) float Ws[16 * N];

    const int t = threadIdx.x;
    const int jg = t % NJG, mg = t / NJG;
    const int m0 = blockIdx.x * MT;

    ull acc[8][4];
    #pragma unroll
    for (int a = 0; a < 8; a++)
        #pragma unroll
        for (int b = 0; b < 4; b++) acc[a][b] = 0ULL;

    for (int k0 = 0; k0 < K; k0 += 16) {
        for (int i = t; i < 16 * MT; i += 256)
            As[i] = A[(size_t)(k0 + i / MT) * NN + m0 + (i % MT)];
        for (int i = t; i < 16 * N; i += 256)
            Ws[i] = W[k0 * N + i];
        __syncthreads();
        #pragma unroll
        for (int kk = 0; kk < 16; kk++) {
            const float* ar = &As[kk * MT + mg];
            const ull* wr = (const ull*)&Ws[kk * N + jg * 8];
            ull w0 = wr[0], w1 = wr[1], w2 = wr[2], w3 = wr[3];
            #pragma unroll
            for (int tt = 0; tt < 8; tt++) {
                float a = ar[tt * MG];
                ull ab = pack2(a, a);
                ffma2(acc[tt][0], ab, w0);
                ffma2(acc[tt][1], ab, w1);
                ffma2(acc[tt][2], ab, w2);
                ffma2(acc[tt][3], ab, w3);
            }
        }
        __syncthreads();
    }

    #pragma unroll
    for (int tt = 0; tt < 8; tt++) {
        size_t node = m0 + mg + tt * MG;
        #pragma unroll
        for (int p = 0; p < 4; p++) {
            float x, y; unpack2(acc[tt][p], x, y);
            int j = jg * 8 + 2 * p;
            x = fmaxf(x + bias[j], 0.0f);
            y = fmaxf(y + bias[j + 1], 0.0f);
            *reinterpret_cast<float2*>(&out[node * N + j]) = make_float2(x, y);
        }
    }
}

// ---------------- pool + FC ----------------
__global__ void pool_fc_kernel(const float* __restrict__ h,
                               const float* __restrict__ fcW1, const float* __restrict__ fcb1,
                               const float* __restrict__ fcW2, const float* __restrict__ fcb2,
                               float* __restrict__ out) {
    __shared__ float red[256];
    __shared__ float pool[64];
    __shared__ float z1[10];
    int g = blockIdx.x, t = threadIdx.x;
    int f = t & 63, part = t >> 6;
    float s = 0.0f;
    for (int n = part; n < NPG; n += 4)
        s += h[(size_t)(g * NPG + n) * 64 + f];
    red[t] = s;
    __syncthreads();
    if (part == 0)
        pool[f] = (red[f] + red[64 + f] + red[128 + f] + red[192 + f]) * (1.0f / NPG);
    __syncthreads();
    if (t < 10) {
        float z = fcb1[t];
        for (int i = 0; i < 64; i++) z += pool[i] * fcW1[i * 10 + t];
        z1[t] = fmaxf(z, 0.0f);
    }
    __syncthreads();
    if (t < 10) {
        float z = fcb2[t];
        for (int j = 0; j < 10; j++) z += z1[j] * fcW2[j * 10 + t];
        out[g * 10 + t] = z;
    }
}

// ---------------- launch ----------------
extern "C" void kernel_launch(void* const* d_in, const int* in_sizes, int n_in,
                              void* d_out, int out_size) {
    const float* x     = (const float*)d_in[0];
    const int*   ei    = (const int*)d_in[1];
    const float* lam   = (const float*)d_in[3];
    const float* W1 = (const float*)d_in[4];  const float* b1 = (const float*)d_in[5];
    const float* W2 = (const float*)d_in[6];  const float* b2 = (const float*)d_in[7];
    const float* W3 = (const float*)d_in[8];  const float* b3 = (const float*)d_in[9];
    const float* fcW1 = (const float*)d_in[10]; const float* fcb1 = (const float*)d_in[11];
    const float* fcW2 = (const float*)d_in[12]; const float* fcb2 = (const float*)d_in[13];
    float* out = (float*)d_out;

    const int SMEM = 2 * NPG * PAD * sizeof(float);  // 73728
    cudaFuncSetAttribute(spmv_kernel<128>, cudaFuncAttributeMaxDynamicSharedMemorySize, SMEM);
    cudaFuncSetAttribute(spmv_kernel<32>,  cudaFuncAttributeMaxDynamicSharedMemorySize, SMEM);
    cudaFuncSetAttribute(spmv_kernel<64>,  cudaFuncAttributeMaxDynamicSharedMemorySize, SMEM);

    float* tx = nullptr; float* ha = nullptr; float* hb = nullptr;
    cudaGetSymbolAddress((void**)&tx, g_tx);
    cudaGetSymbolAddress((void**)&ha, g_ha);
    cudaGetSymbolAddress((void**)&hb, g_hb);

    zero_kernel<<<NN / 256, 256>>>();                       // 0
    deg_kernel<<<NE / 256, 256>>>(ei);                      // 1
    fill_kernel<<<NE / 256, 256>>>(ei, lam);                // 2

    spmv_kernel<128><<<dim3(16, NG), 1024, SMEM>>>(x, lam, tx);   // 3  <- ncu captures this
    gemm_kernel<640, 32, 512><<<NN / 512, 256>>>(tx, W1, b1, ha);

    spmv_kernel<32><<<dim3(4, NG), 1024, SMEM>>>(ha, lam, tx);
    gemm_kernel<160, 64, 256><<<NN / 256, 256>>>(tx, W2, b2, hb);

    spmv_kernel<64><<<dim3(8, NG), 1024, SMEM>>>(hb, lam, tx);
    gemm_kernel<320, 64, 256><<<NN / 256, 256>>>(tx, W3, b3, ha);

    pool_fc_kernel<<<NG, 256>>>(ha, fcW1, fcb1, fcW2, fcb2, out);
}

// round 7
// speedup vs baseline: 1.0268x; 1.0268x over previous
#include <cuda_runtime.h>
#include <cuda_bf16.h>

#define NN      65536
#define NE      1048576
#define NG      64
#define NPG     1024
#define CF      8
#define PAD2    10      // floats per smem row (40B, float2-aligned)
#define RSTRIDE 80      // edge slots per node (deg ~Poisson(16); over-read pad)

typedef unsigned long long ull;

__device__ int   g_deg[NN];                     // out-degree (for dis)
__device__ int   g_cnt[NN];                     // in-degree  (row length)
__device__ int   g_cur[NN];
__device__ int2  g_edges[(size_t)NN * RSTRIDE]; // zero-init; pad slots never written
__device__ float g_tx[640ull * NN];
__device__ float g_ha[(size_t)NN * 64];
__device__ float g_hb[(size_t)NN * 64];

__device__ __forceinline__ ull pack2(float x, float y) {
    ull r; asm("mov.b64 %0, {%1, %2};" : "=l"(r) : "f"(x), "f"(y)); return r;
}
__device__ __forceinline__ void ffma2(ull& d, ull a, ull b) {
    asm("fma.rn.f32x2 %0, %1, %2, %0;" : "+l"(d) : "l"(a), "l"(b));
}
__device__ __forceinline__ void unpack2(ull v, float& x, float& y) {
    asm("mov.b64 {%0, %1}, %2;" : "=f"(x), "=f"(y) : "l"(v));
}

// ---------------- prep ----------------
__global__ void zero_kernel() {
    int i = blockIdx.x * blockDim.x + threadIdx.x;
    if (i < NN) { g_deg[i] = 0; g_cnt[i] = 0; g_cur[i] = 0; }
}

__global__ void deg_kernel(const int* __restrict__ ei) {
    int e = blockIdx.x * blockDim.x + threadIdx.x;
    if (e >= NE) return;
    int s = ei[e], d = ei[NE + e];
    if (s != d) { atomicAdd(&g_deg[s], 1); atomicAdd(&g_cnt[d], 1); }
}

__global__ void fill_kernel(const int* __restrict__ ei,
                            const float* __restrict__ lam) {
    int e = blockIdx.x * blockDim.x + threadIdx.x;
    if (e >= NE) return;
    int s = ei[e], d = ei[NE + e];
    if (s == d) return;
    int od = g_deg[d];
    float dd = (od > 0) ? rsqrtf((float)od) : 0.0f;
    float w = -2.0f * rsqrtf((float)g_deg[s]) * dd / lam[s >> 10];
    int slot = atomicAdd(&g_cur[d], 1);
    // store PRE-SCALED row byte offset: src_local * PAD2 * 4
    g_edges[(size_t)d * RSTRIDE + slot] =
        make_int2((s & (NPG - 1)) * (PAD2 * 4), __float_as_int(w));
}

// ---------------- Chebyshev recurrence ----------------
// CTA = (8-feature chunk, graph). 1024 threads, 2 CTAs/SM.
// Warp owns 32 nodes sequentially. Per node: 8 edge streams (sub=lane>>2),
// each lane handles a feature PAIR (fp=lane&3) via float2.
template<int F>
__global__ void __launch_bounds__(1024, 2)
spmv_kernel(const float* __restrict__ hin, const float* __restrict__ lam,
            float* __restrict__ txout) {
    extern __shared__ float sm[];
    float* buf0 = sm;                  // [1024][PAD2]
    float* buf1 = sm + NPG * PAD2;

    const int g = blockIdx.y, cb = blockIdx.x * CF, t = threadIdx.x;
    const int gbase = g * NPG;
    const float diag = 2.0f / lam[g] - 1.0f;

    const float* hp = hin + (size_t)gbase * F + cb;
    #pragma unroll
    for (int r = 0; r < CF; r++) {
        int i = r * 1024 + t;
        buf0[(i >> 3) * PAD2 + (i & 7)] = hp[(i >> 3) * F + (i & 7)];
    }
    __syncthreads();

    #pragma unroll
    for (int f = 0; f < CF; f++)
        txout[(size_t)(cb + f) * NN + gbase + t] = buf0[t * PAD2 + f];

    const int lane = t & 31, warp = t >> 5;
    const int fp = lane & 3, sub = lane >> 2;
    const int mydeg = g_cnt[gbase + warp * 32 + lane];   // deg of node p==lane
    float* cur = buf0; float* oth = buf1;

    for (int k = 1; k < 5; k++) {
        #pragma unroll 1
        for (int p = 0; p < 32; p++) {
            const int dloc = warp * 32 + p;
            const int deg = __shfl_sync(0xffffffffu, mydeg, p);
            const int trips = (deg + 7) >> 3;
            const char* base =
                (const char*)(g_edges + (size_t)(gbase + dloc) * RSTRIDE) + sub * 8;
            float ax = 0.0f, ay = 0.0f;
            #pragma unroll 1
            for (int i = 0; i < trips; i += 2) {
                int2 e0 = *(const int2*)(base + (size_t)i * 64);
                int2 e1 = *(const int2*)(base + (size_t)i * 64 + 64);
                float2 v0 = *(const float2*)((const char*)cur + e0.x + fp * 8);
                float2 v1 = *(const float2*)((const char*)cur + e1.x + fp * 8);
                float w0 = __int_as_float(e0.y), w1 = __int_as_float(e1.y);
                ax = fmaf(w0, v0.x, ax); ay = fmaf(w0, v0.y, ay);
                ax = fmaf(w1, v1.x, ax); ay = fmaf(w1, v1.y, ay);
            }
            ax += __shfl_xor_sync(0xffffffffu, ax, 4);
            ay += __shfl_xor_sync(0xffffffffu, ay, 4);
            ax += __shfl_xor_sync(0xffffffffu, ax, 8);
            ay += __shfl_xor_sync(0xffffffffu, ay, 8);
            ax += __shfl_xor_sync(0xffffffffu, ax, 16);
            ay += __shfl_xor_sync(0xffffffffu, ay, 16);
            if (sub == 0) {
                float2* op = (float2*)(oth + dloc * PAD2 + fp * 2);
                float2 c = *(const float2*)(cur + dloc * PAD2 + fp * 2);
                float lx = fmaf(diag, c.x, ax);
                float ly = fmaf(diag, c.y, ay);
                if (k > 1) {
                    float2 o = *op;
                    lx = 2.0f * lx - o.x;
                    ly = 2.0f * ly - o.y;
                }
                *op = make_float2(lx, ly);
            }
        }
        __syncthreads();
        #pragma unroll
        for (int f = 0; f < CF; f++)
            txout[(size_t)(k * F + cb + f) * NN + gbase + t] = oth[t * PAD2 + f];
        float* tmp = cur; cur = oth; oth = tmp;
        __syncthreads();
    }
}

// ---------------- GEMM: out = relu(A^T W + b), A:[K][NN], W:[K][N] ----------------
template<int K, int N, int MT>
__global__ void __launch_bounds__(256)
gemm_kernel(const float* __restrict__ A, const float* __restrict__ W,
            const float* __restrict__ bias, float* __restrict__ out) {
    constexpr int NJG = N / 8;
    constexpr int MG  = MT / 8;
    static_assert(MG * NJG == 256, "cfg");
    __shared__ __align__(16) float As[16 * MT];
    __shared__ __align__(16) float Ws[16 * N];

    const int t = threadIdx.x;
    const int jg = t % NJG, mg = t / NJG;
    const int m0 = blockIdx.x * MT;

    ull acc[8][4];
    #pragma unroll
    for (int a = 0; a < 8; a++)
        #pragma unroll
        for (int b = 0; b < 4; b++) acc[a][b] = 0ULL;

    for (int k0 = 0; k0 < K; k0 += 16) {
        for (int i = t; i < 16 * MT; i += 256)
            As[i] = A[(size_t)(k0 + i / MT) * NN + m0 + (i % MT)];
        for (int i = t; i < 16 * N; i += 256)
            Ws[i] = W[k0 * N + i];
        __syncthreads();
        #pragma unroll
        for (int kk = 0; kk < 16; kk++) {
            const float* ar = &As[kk * MT + mg];
            const ull* wr = (const ull*)&Ws[kk * N + jg * 8];
            ull w0 = wr[0], w1 = wr[1], w2 = wr[2], w3 = wr[3];
            #pragma unroll
            for (int tt = 0; tt < 8; tt++) {
                float a = ar[tt * MG];
                ull ab = pack2(a, a);
                ffma2(acc[tt][0], ab, w0);
                ffma2(acc[tt][1], ab, w1);
                ffma2(acc[tt][2], ab, w2);
                ffma2(acc[tt][3], ab, w3);
            }
        }
        __syncthreads();
    }

    #pragma unroll
    for (int tt = 0; tt < 8; tt++) {
        size_t node = m0 + mg + tt * MG;
        #pragma unroll
        for (int p = 0; p < 4; p++) {
            float x, y; unpack2(acc[tt][p], x, y);
            int j = jg * 8 + 2 * p;
            x = fmaxf(x + bias[j], 0.0f);
            y = fmaxf(y + bias[j + 1], 0.0f);
            *reinterpret_cast<float2*>(&out[node * N + j]) = make_float2(x, y);
        }
    }
}

// ---------------- pool + FC ----------------
__global__ void pool_fc_kernel(const float* __restrict__ h,
                               const float* __restrict__ fcW1, const float* __restrict__ fcb1,
                               const float* __restrict__ fcW2, const float* __restrict__ fcb2,
                               float* __restrict__ out) {
    __shared__ float red[256];
    __shared__ float pool[64];
    __shared__ float z1[10];
    int g = blockIdx.x, t = threadIdx.x;
    int f = t & 63, part = t >> 6;
    float s = 0.0f;
    for (int n = part; n < NPG; n += 4)
        s += h[(size_t)(g * NPG + n) * 64 + f];
    red[t] = s;
    __syncthreads();
    if (part == 0)
        pool[f] = (red[f] + red[64 + f] + red[128 + f] + red[192 + f]) * (1.0f / NPG);
    __syncthreads();
    if (t < 10) {
        float z = fcb1[t];
        for (int i = 0; i < 64; i++) z += pool[i] * fcW1[i * 10 + t];
        z1[t] = fmaxf(z, 0.0f);
    }
    __syncthreads();
    if (t < 10) {
        float z = fcb2[t];
        for (int j = 0; j < 10; j++) z += z1[j] * fcW2[j * 10 + t];
        out[g * 10 + t] = z;
    }
}

// ---------------- launch ----------------
extern "C" void kernel_launch(void* const* d_in, const int* in_sizes, int n_in,
                              void* d_out, int out_size) {
    const float* x     = (const float*)d_in[0];
    const int*   ei    = (const int*)d_in[1];
    const float* lam   = (const float*)d_in[3];
    const float* W1 = (const float*)d_in[4];  const float* b1 = (const float*)d_in[5];
    const float* W2 = (const float*)d_in[6];  const float* b2 = (const float*)d_in[7];
    const float* W3 = (const float*)d_in[8];  const float* b3 = (const float*)d_in[9];
    const float* fcW1 = (const float*)d_in[10]; const float* fcb1 = (const float*)d_in[11];
    const float* fcW2 = (const float*)d_in[12]; const float* fcb2 = (const float*)d_in[13];
    float* out = (float*)d_out;

    const int SMEM = 2 * NPG * PAD2 * sizeof(float);  // 81920
    cudaFuncSetAttribute(spmv_kernel<128>, cudaFuncAttributeMaxDynamicSharedMemorySize, SMEM);
    cudaFuncSetAttribute(spmv_kernel<32>,  cudaFuncAttributeMaxDynamicSharedMemorySize, SMEM);
    cudaFuncSetAttribute(spmv_kernel<64>,  cudaFuncAttributeMaxDynamicSharedMemorySize, SMEM);

    float* tx = nullptr; float* ha = nullptr; float* hb = nullptr;
    cudaGetSymbolAddress((void**)&tx, g_tx);
    cudaGetSymbolAddress((void**)&ha, g_ha);
    cudaGetSymbolAddress((void**)&hb, g_hb);

    zero_kernel<<<NN / 256, 256>>>();                       // 0
    deg_kernel<<<NE / 256, 256>>>(ei);                      // 1
    fill_kernel<<<NE / 256, 256>>>(ei, lam);                // 2

    spmv_kernel<128><<<dim3(16, NG), 1024, SMEM>>>(x, lam, tx);   // 3 <- ncu captures this
    gemm_kernel<640, 32, 512><<<NN / 512, 256>>>(tx, W1, b1, ha);

    spmv_kernel<32><<<dim3(4, NG), 1024, SMEM>>>(ha, lam, tx);
    gemm_kernel<160, 64, 256><<<NN / 256, 256>>>(tx, W2, b2, hb);

    spmv_kernel<64><<<dim3(8, NG), 1024, SMEM>>>(hb, lam, tx);
    gemm_kernel<320, 64, 256><<<NN / 256, 256>>>(tx, W3, b3, ha);

    pool_fc_kernel<<<NG, 256>>>(ha, fcW1, fcb1, fcW2, fcb2, out);
}

// round 8
// speedup vs baseline: 1.0345x; 1.0076x over previous
#include <cuda_runtime.h>
#include <cuda_bf16.h>

#define NN      65536
#define NE      1048576
#define NG      64
#define NPG     1024
#define CF      16
#define PAD     17      // floats per smem row: 68B, odd 4B-stride -> full bank spread
#define RSTRIDE 80      // edge slots per node

typedef unsigned long long ull;

__device__ int   g_deg[NN];
__device__ int   g_cnt[NN];
__device__ int   g_cur[NN];
__device__ int2  g_edges[(size_t)NN * RSTRIDE]; // zero-init; pads never written
__device__ float g_tx[640ull * NN];
__device__ float g_ha[(size_t)NN * 64];
__device__ float g_hb[(size_t)NN * 64];

__device__ __forceinline__ ull pack2(float x, float y) {
    ull r; asm("mov.b64 %0, {%1, %2};" : "=l"(r) : "f"(x), "f"(y)); return r;
}
__device__ __forceinline__ void ffma2(ull& d, ull a, ull b) {
    asm("fma.rn.f32x2 %0, %1, %2, %0;" : "+l"(d) : "l"(a), "l"(b));
}
__device__ __forceinline__ void unpack2(ull v, float& x, float& y) {
    asm("mov.b64 {%0, %1}, %2;" : "=f"(x), "=f"(y) : "l"(v));
}

// ---------------- prep ----------------
__global__ void zero_kernel() {
    int i = blockIdx.x * blockDim.x + threadIdx.x;
    if (i < NN) { g_deg[i] = 0; g_cnt[i] = 0; g_cur[i] = 0; }
}

__global__ void deg_kernel(const int* __restrict__ ei) {
    int e = blockIdx.x * blockDim.x + threadIdx.x;
    if (e >= NE) return;
    int s = ei[e], d = ei[NE + e];
    if (s != d) { atomicAdd(&g_deg[s], 1); atomicAdd(&g_cnt[d], 1); }
}

__global__ void fill_kernel(const int* __restrict__ ei,
                            const float* __restrict__ lam) {
    int e = blockIdx.x * blockDim.x + threadIdx.x;
    if (e >= NE) return;
    int s = ei[e], d = ei[NE + e];
    if (s == d) return;
    int od = g_deg[d];
    float dd = (od > 0) ? rsqrtf((float)od) : 0.0f;
    float w = -2.0f * rsqrtf((float)g_deg[s]) * dd / lam[s >> 10];
    int slot = atomicAdd(&g_cur[d], 1);
    // PRE-SCALED row byte offset: src_local * PAD * 4 (= *68)
    g_edges[(size_t)d * RSTRIDE + slot] =
        make_int2((s & (NPG - 1)) * (PAD * 4), __float_as_int(w));
}

// ---------------- Chebyshev recurrence ----------------
// CTA = (16-feature chunk, graph). 1024 threads, 1 CTA/SM (136KB smem).
// Warp owns 32 nodes sequentially. Per node: 4 edge streams (sub=lane>>3);
// each lane handles TWO features: fl=lane&7 and fl+8 (scalar LDS, +0/+32B).
template<int F>
__global__ void __launch_bounds__(1024, 1)
spmv_kernel(const float* __restrict__ hin, const float* __restrict__ lam,
            float* __restrict__ txout) {
    extern __shared__ float sm[];
    float* buf0 = sm;                   // [1024][PAD]
    float* buf1 = sm + NPG * PAD;

    const int g = blockIdx.y, cb = blockIdx.x * CF, t = threadIdx.x;
    const int gbase = g * NPG;
    const float diag = 2.0f / lam[g] - 1.0f;

    const float* hp = hin + (size_t)gbase * F + cb;
    #pragma unroll
    for (int r = 0; r < CF; r++) {
        int i = r * 1024 + t;
        buf0[(i >> 4) * PAD + (i & 15)] = hp[(i >> 4) * F + (i & 15)];
    }
    __syncthreads();

    #pragma unroll
    for (int f = 0; f < CF; f++)
        txout[(size_t)(cb + f) * NN + gbase + t] = buf0[t * PAD + f];

    const int lane = t & 31, warp = t >> 5;
    const int fl = lane & 7, sub = lane >> 3;
    const int mydeg = g_cnt[gbase + warp * 32 + lane];
    float* cur = buf0; float* oth = buf1;

    for (int k = 1; k < 5; k++) {
        const char* curc = (const char*)cur + fl * 4;
        #pragma unroll 1
        for (int p = 0; p < 32; p++) {
            const int dloc = warp * 32 + p;
            const int deg = __shfl_sync(0xffffffffu, mydeg, p);
            const int trips = (deg + 3) >> 2;       // edges per sub (ceil)
            const char* base =
                (const char*)(g_edges + (size_t)(gbase + dloc) * RSTRIDE) + sub * 8;
            float ax = 0.0f, ay = 0.0f;
            #pragma unroll 1
            for (int i = 0; i < trips; i += 2) {
                int2 e0 = *(const int2*)(base + (size_t)i * 32);
                int2 e1 = *(const int2*)(base + (size_t)i * 32 + 32);
                float w0 = __int_as_float(e0.y), w1 = __int_as_float(e1.y);
                float v0a = *(const float*)(curc + e0.x);
                float v0b = *(const float*)(curc + e0.x + 32);
                float v1a = *(const float*)(curc + e1.x);
                float v1b = *(const float*)(curc + e1.x + 32);
                ax = fmaf(w0, v0a, ax); ay = fmaf(w0, v0b, ay);
                ax = fmaf(w1, v1a, ax); ay = fmaf(w1, v1b, ay);
            }
            ax += __shfl_xor_sync(0xffffffffu, ax, 8);
            ay += __shfl_xor_sync(0xffffffffu, ay, 8);
            ax += __shfl_xor_sync(0xffffffffu, ax, 16);
            ay += __shfl_xor_sync(0xffffffffu, ay, 16);
            if (lane < 8) {
                int idx = dloc * PAD + fl;
                float ca = cur[idx], cb2 = cur[idx + 8];
                float lx = fmaf(diag, ca, ax);
                float ly = fmaf(diag, cb2, ay);
                if (k > 1) {
                    lx = 2.0f * lx - oth[idx];
                    ly = 2.0f * ly - oth[idx + 8];
                }
                oth[idx] = lx;
                oth[idx + 8] = ly;
            }
        }
        __syncthreads();
        #pragma unroll
        for (int f = 0; f < CF; f++)
            txout[(size_t)(k * F + cb + f) * NN + gbase + t] = oth[t * PAD + f];
        float* tmp = cur; cur = oth; oth = tmp;
        __syncthreads();
    }
}

// ---------------- GEMM: out = relu(A^T W + b), A:[K][NN], W:[K][N] ----------------
template<int K, int N, int MT>
__global__ void __launch_bounds__(256)
gemm_kernel(const float* __restrict__ A, const float* __restrict__ W,
            const float* __restrict__ bias, float* __restrict__ out) {
    constexpr int NJG = N / 8;
    constexpr int MG  = MT / 8;
    static_assert(MG * NJG == 256, "cfg");
    __shared__ __align__(16) float As[16 * MT];
    __shared__ __align__(16) float Ws[16 * N];

    const int t = threadIdx.x;
    const int jg = t % NJG, mg = t / NJG;
    const int m0 = blockIdx.x * MT;

    ull acc[8][4];
    #pragma unroll
    for (int a = 0; a < 8; a++)
        #pragma unroll
        for (int b = 0; b < 4; b++) acc[a][b] = 0ULL;

    for (int k0 = 0; k0 < K; k0 += 16) {
        for (int i = t; i < 16 * MT; i += 256)
            As[i] = A[(size_t)(k0 + i / MT) * NN + m0 + (i % MT)];
        for (int i = t; i < 16 * N; i += 256)
            Ws[i] = W[k0 * N + i];
        __syncthreads();
        #pragma unroll
        for (int kk = 0; kk < 16; kk++) {
            const float* ar = &As[kk * MT + mg];
            const ull* wr = (const ull*)&Ws[kk * N + jg * 8];
            ull w0 = wr[0], w1 = wr[1], w2 = wr[2], w3 = wr[3];
            #pragma unroll
            for (int tt = 0; tt < 8; tt++) {
                float a = ar[tt * MG];
                ull ab = pack2(a, a);
                ffma2(acc[tt][0], ab, w0);
                ffma2(acc[tt][1], ab, w1);
                ffma2(acc[tt][2], ab, w2);
                ffma2(acc[tt][3], ab, w3);
            }
        }
        __syncthreads();
    }

    #pragma unroll
    for (int tt = 0; tt < 8; tt++) {
        size_t node = m0 + mg + tt * MG;
        #pragma unroll
        for (int p = 0; p < 4; p++) {
            float x, y; unpack2(acc[tt][p], x, y);
            int j = jg * 8 + 2 * p;
            x = fmaxf(x + bias[j], 0.0f);
            y = fmaxf(y + bias[j + 1], 0.0f);
            *reinterpret_cast<float2*>(&out[node * N + j]) = make_float2(x, y);
        }
    }
}

// ---------------- pool + FC ----------------
__global__ void pool_fc_kernel(const float* __restrict__ h,
                               const float* __restrict__ fcW1, const float* __restrict__ fcb1,
                               const float* __restrict__ fcW2, const float* __restrict__ fcb2,
                               float* __restrict__ out) {
    __shared__ float red[256];
    __shared__ float pool[64];
    __shared__ float z1[10];
    int g = blockIdx.x, t = threadIdx.x;
    int f = t & 63, part = t >> 6;
    float s = 0.0f;
    for (int n = part; n < NPG; n += 4)
        s += h[(size_t)(g * NPG + n) * 64 + f];
    red[t] = s;
    __syncthreads();
    if (part == 0)
        pool[f] = (red[f] + red[64 + f] + red[128 + f] + red[192 + f]) * (1.0f / NPG);
    __syncthreads();
    if (t < 10) {
        float z = fcb1[t];
        for (int i = 0; i < 64; i++) z += pool[i] * fcW1[i * 10 + t];
        z1[t] = fmaxf(z, 0.0f);
    }
    __syncthreads();
    if (t < 10) {
        float z = fcb2[t];
        for (int j = 0; j < 10; j++) z += z1[j] * fcW2[j * 10 + t];
        out[g * 10 + t] = z;
    }
}

// ---------------- launch ----------------
extern "C" void kernel_launch(void* const* d_in, const int* in_sizes, int n_in,
                              void* d_out, int out_size) {
    const float* x     = (const float*)d_in[0];
    const int*   ei    = (const int*)d_in[1];
    const float* lam   = (const float*)d_in[3];
    const float* W1 = (const float*)d_in[4];  const float* b1 = (const float*)d_in[5];
    const float* W2 = (const float*)d_in[6];  const float* b2 = (const float*)d_in[7];
    const float* W3 = (const float*)d_in[8];  const float* b3 = (const float*)d_in[9];
    const float* fcW1 = (const float*)d_in[10]; const float* fcb1 = (const float*)d_in[11];
    const float* fcW2 = (const float*)d_in[12]; const float* fcb2 = (const float*)d_in[13];
    float* out = (float*)d_out;

    const int SMEM = 2 * NPG * PAD * sizeof(float);  // 139264
    cudaFuncSetAttribute(spmv_kernel<128>, cudaFuncAttributeMaxDynamicSharedMemorySize, SMEM);
    cudaFuncSetAttribute(spmv_kernel<32>,  cudaFuncAttributeMaxDynamicSharedMemorySize, SMEM);
    cudaFuncSetAttribute(spmv_kernel<64>,  cudaFuncAttributeMaxDynamicSharedMemorySize, SMEM);

    float* tx = nullptr; float* ha = nullptr; float* hb = nullptr;
    cudaGetSymbolAddress((void**)&tx, g_tx);
    cudaGetSymbolAddress((void**)&ha, g_ha);
    cudaGetSymbolAddress((void**)&hb, g_hb);

    zero_kernel<<<NN / 256, 256>>>();                       // 0
    deg_kernel<<<NE / 256, 256>>>(ei);                      // 1
    fill_kernel<<<NE / 256, 256>>>(ei, lam);                // 2

    spmv_kernel<128><<<dim3(8, NG), 1024, SMEM>>>(x, lam, tx);    // 3 <- ncu captures this
    gemm_kernel<640, 32, 512><<<NN / 512, 256>>>(tx, W1, b1, ha);

    spmv_kernel<32><<<dim3(2, NG), 1024, SMEM>>>(ha, lam, tx);
    gemm_kernel<160, 64, 256><<<NN / 256, 256>>>(tx, W2, b2, hb);

    spmv_kernel<64><<<dim3(4, NG), 1024, SMEM>>>(hb, lam, tx);
    gemm_kernel<320, 64, 256><<<NN / 256, 256>>>(tx, W3, b3, ha);

    pool_fc_kernel<<<NG, 256>>>(ha, fcW1, fcb1, fcW2, fcb2, out);
}

// round 9
// speedup vs baseline: 1.3050x; 1.2614x over previous
#include <cuda_runtime.h>
#include <cuda_bf16.h>

#define NN      65536
#define NE      1048576
#define NG      64
#define NPG     1024
#define CF      8
#define RSTRIDE 64      // edge slots per node

typedef unsigned long long ull;

__device__ int   g_deg[NN];
__device__ int   g_cnt[NN];
__device__ int   g_cur[NN];
// interleaved: [(node/8)][slot][node%8]; zero-init; pad slots never written
__device__ int2  g_edges[(size_t)NN * RSTRIDE];
__device__ float g_tx[640ull * NN];
__device__ float g_ha[(size_t)NN * 64];
__device__ float g_hb[(size_t)NN * 64];

__device__ __forceinline__ ull pack2(float x, float y) {
    ull r; asm("mov.b64 %0, {%1, %2};" : "=l"(r) : "f"(x), "f"(y)); return r;
}
__device__ __forceinline__ void ffma2(ull& d, ull a, ull b) {
    asm("fma.rn.f32x2 %0, %1, %2, %0;" : "+l"(d) : "l"(a), "l"(b));
}
__device__ __forceinline__ void unpack2(ull v, float& x, float& y) {
    asm("mov.b64 {%0, %1}, %2;" : "=f"(x), "=f"(y) : "l"(v));
}

// ---------------- prep ----------------
__global__ void zero_kernel() {
    int i = blockIdx.x * blockDim.x + threadIdx.x;
    if (i < NN) { g_deg[i] = 0; g_cnt[i] = 0; g_cur[i] = 0; }
}

__global__ void deg_kernel(const int* __restrict__ ei) {
    int e = blockIdx.x * blockDim.x + threadIdx.x;
    if (e >= NE) return;
    int s = ei[e], d = ei[NE + e];
    if (s != d) { atomicAdd(&g_deg[s], 1); atomicAdd(&g_cnt[d], 1); }
}

__global__ void fill_kernel(const int* __restrict__ ei,
                            const float* __restrict__ lam) {
    int e = blockIdx.x * blockDim.x + threadIdx.x;
    if (e >= NE) return;
    int s = ei[e], d = ei[NE + e];
    if (s == d) return;
    int od = g_deg[d];
    float dd = (od > 0) ? rsqrtf((float)od) : 0.0f;
    float w = -2.0f * rsqrtf((float)g_deg[s]) * dd / lam[s >> 10];
    int slot = atomicAdd(&g_cur[d], 1);
    int sloc = s & (NPG - 1);
    // smem byte offset of src row, with swizzle class baked in (bits 3-4)
    int eoff = (sloc << 5) | (((sloc >> 2) & 3) << 3);
    size_t idx = (size_t)(d & ~7) * RSTRIDE + slot * 8 + (d & 7);
    g_edges[idx] = make_int2(eoff, __float_as_int(w));
}

// ---------------- Chebyshev recurrence ----------------
// CTA = (8-feature chunk, graph), 1024 threads, 2 CTAs/SM (64KB smem).
// Warp iter processes 8 NODES in parallel: sub=lane>>2 node, fp=lane&3 feature
// pair (float2). No cross-lane reduction; all 32 lanes write back directly.
// smem rows: tight 32B, pair p of row r stored at pair-slot (p ^ ((r>>2)&3)).
template<int F>
__global__ void __launch_bounds__(1024, 2)
spmv_kernel(const float* __restrict__ hin, const float* __restrict__ lam,
            float* __restrict__ txout) {
    extern __shared__ float sm[];
    float* buf0 = sm;                   // [1024][8] swizzled
    float* buf1 = sm + NPG * 8;

    const int g = blockIdx.y, cb = blockIdx.x * CF, t = threadIdx.x;
    const int gbase = g * NPG;
    const float diag = 2.0f / lam[g] - 1.0f;

    // load chunk -> swizzled smem
    const float* hp = hin + (size_t)gbase * F + cb;
    #pragma unroll
    for (int r = 0; r < CF; r++) {
        int i = r * 1024 + t;
        int row = i >> 3, f = i & 7;
        int sw = ((f >> 1) ^ ((row >> 2) & 3)) * 2 + (f & 1);
        buf0[row * 8 + sw] = hp[row * F + f];
    }
    __syncthreads();

    // Tx0 -> transposed global
    {
        int s_t = (t >> 2) & 3;
        #pragma unroll
        for (int f = 0; f < CF; f++) {
            int sw = ((f >> 1) ^ s_t) * 2 + (f & 1);
            txout[(size_t)(cb + f) * NN + gbase + t] = buf0[t * 8 + sw];
        }
    }

    const int lane = t & 31, warp = t >> 5;
    const int fp8 = (lane & 3) * 8;
    const int sub = lane >> 2;
    int v = g_cnt[gbase + warp * 32 + lane];
    v = max(v, __shfl_xor_sync(0xffffffffu, v, 1));
    v = max(v, __shfl_xor_sync(0xffffffffu, v, 2));
    v = max(v, __shfl_xor_sync(0xffffffffu, v, 4));   // max deg per 8-lane group

    float* cur = buf0; float* oth = buf1;
    for (int k = 1; k < 5; k++) {
        const char* curb = (const char*)cur;
        #pragma unroll 1
        for (int p = 0; p < 4; p++) {
            const int gdeg = __shfl_sync(0xffffffffu, v, p * 8);
            const int node8 = warp * 32 + p * 8;
            const char* ebase =
                (const char*)(g_edges + (size_t)(gbase + node8) * RSTRIDE) + sub * 8;
            float ax = 0.0f, ay = 0.0f;
            #pragma unroll 1
            for (int i = 0; i < gdeg; i += 2) {
                int2 e0 = *(const int2*)(ebase + i * 64);
                int2 e1 = *(const int2*)(ebase + i * 64 + 64);
                float2 v0 = *(const float2*)(curb + (e0.x ^ fp8));
                float2 v1 = *(const float2*)(curb + (e1.x ^ fp8));
                float w0 = __int_as_float(e0.y), w1 = __int_as_float(e1.y);
                ax = fmaf(w0, v0.x, ax); ay = fmaf(w0, v0.y, ay);
                ax = fmaf(w1, v1.x, ax); ay = fmaf(w1, v1.y, ay);
            }
            const int dloc = node8 + sub;
            const int swb = fp8 ^ (((dloc >> 2) & 3) << 3);
            float2 c = *(const float2*)((const char*)cur + dloc * 32 + swb);
            float lx = fmaf(diag, c.x, ax);
            float ly = fmaf(diag, c.y, ay);
            float2* op = (float2*)((char*)oth + dloc * 32 + swb);
            if (k > 1) { float2 o = *op; lx = 2.0f * lx - o.x; ly = 2.0f * ly - o.y; }
            *op = make_float2(lx, ly);
        }
        __syncthreads();
        int s_t = (t >> 2) & 3;
        #pragma unroll
        for (int f = 0; f < CF; f++) {
            int sw = ((f >> 1) ^ s_t) * 2 + (f & 1);
            txout[(size_t)(k * F + cb + f) * NN + gbase + t] = oth[t * 8 + sw];
        }
        float* tmp = cur; cur = oth; oth = tmp;
        __syncthreads();
    }
}

// ---------------- GEMM: out = relu(A^T W + b), A:[K][NN], W:[K][N] ----------------
template<int K, int N, int MT>
__global__ void __launch_bounds__(256)
gemm_kernel(const float* __restrict__ A, const float* __restrict__ W,
            const float* __restrict__ bias, float* __restrict__ out) {
    constexpr int NJG = N / 8;
    constexpr int MG  = MT / 8;
    static_assert(MG * NJG == 256, "cfg");
    __shared__ __align__(16) float As[16 * MT];
    __shared__ __align__(16) float Ws[16 * N];

    const int t = threadIdx.x;
    const int jg = t % NJG, mg = t / NJG;
    const int m0 = blockIdx.x * MT;

    ull acc[8][4];
    #pragma unroll
    for (int a = 0; a < 8; a++)
        #pragma unroll
        for (int b = 0; b < 4; b++) acc[a][b] = 0ULL;

    for (int k0 = 0; k0 < K; k0 += 16) {
        for (int i = t; i < 16 * MT; i += 256)
            As[i] = A[(size_t)(k0 + i / MT) * NN + m0 + (i % MT)];
        for (int i = t; i < 16 * N; i += 256)
            Ws[i] = W[k0 * N + i];
        __syncthreads();
        #pragma unroll
        for (int kk = 0; kk < 16; kk++) {
            const float* ar = &As[kk * MT + mg];
            const ull* wr = (const ull*)&Ws[kk * N + jg * 8];
            ull w0 = wr[0], w1 = wr[1], w2 = wr[2], w3 = wr[3];
            #pragma unroll
            for (int tt = 0; tt < 8; tt++) {
                float a = ar[tt * MG];
                ull ab = pack2(a, a);
                ffma2(acc[tt][0], ab, w0);
                ffma2(acc[tt][1], ab, w1);
                ffma2(acc[tt][2], ab, w2);
                ffma2(acc[tt][3], ab, w3);
            }
        }
        __syncthreads();
    }

    #pragma unroll
    for (int tt = 0; tt < 8; tt++) {
        size_t node = m0 + mg + tt * MG;
        #pragma unroll
        for (int p = 0; p < 4; p++) {
            float x, y; unpack2(acc[tt][p], x, y);
            int j = jg * 8 + 2 * p;
            x = fmaxf(x + bias[j], 0.0f);
            y = fmaxf(y + bias[j + 1], 0.0f);
            *reinterpret_cast<float2*>(&out[node * N + j]) = make_float2(x, y);
        }
    }
}

// ---------------- pool + FC ----------------
__global__ void pool_fc_kernel(const float* __restrict__ h,
                               const float* __restrict__ fcW1, const float* __restrict__ fcb1,
                               const float* __restrict__ fcW2, const float* __restrict__ fcb2,
                               float* __restrict__ out) {
    __shared__ float red[256];
    __shared__ float pool[64];
    __shared__ float z1[10];
    int g = blockIdx.x, t = threadIdx.x;
    int f = t & 63, part = t >> 6;
    float s = 0.0f;
    for (int n = part; n < NPG; n += 4)
        s += h[(size_t)(g * NPG + n) * 64 + f];
    red[t] = s;
    __syncthreads();
    if (part == 0)
        pool[f] = (red[f] + red[64 + f] + red[128 + f] + red[192 + f]) * (1.0f / NPG);
    __syncthreads();
    if (t < 10) {
        float z = fcb1[t];
        for (int i = 0; i < 64; i++) z += pool[i] * fcW1[i * 10 + t];
        z1[t] = fmaxf(z, 0.0f);
    }
    __syncthreads();
    if (t < 10) {
        float z = fcb2[t];
        for (int j = 0; j < 10; j++) z += z1[j] * fcW2[j * 10 + t];
        out[g * 10 + t] = z;
    }
}

// ---------------- launch ----------------
extern "C" void kernel_launch(void* const* d_in, const int* in_sizes, int n_in,
                              void* d_out, int out_size) {
    const float* x     = (const float*)d_in[0];
    const int*   ei    = (const int*)d_in[1];
    const float* lam   = (const float*)d_in[3];
    const float* W1 = (const float*)d_in[4];  const float* b1 = (const float*)d_in[5];
    const float* W2 = (const float*)d_in[6];  const float* b2 = (const float*)d_in[7];
    const float* W3 = (const float*)d_in[8];  const float* b3 = (const float*)d_in[9];
    const float* fcW1 = (const float*)d_in[10]; const float* fcb1 = (const float*)d_in[11];
    const float* fcW2 = (const float*)d_in[12]; const float* fcb2 = (const float*)d_in[13];
    float* out = (float*)d_out;

    const int SMEM = 2 * NPG * CF * sizeof(float);  // 65536
    cudaFuncSetAttribute(spmv_kernel<128>, cudaFuncAttributeMaxDynamicSharedMemorySize, SMEM);
    cudaFuncSetAttribute(spmv_kernel<32>,  cudaFuncAttributeMaxDynamicSharedMemorySize, SMEM);
    cudaFuncSetAttribute(spmv_kernel<64>,  cudaFuncAttributeMaxDynamicSharedMemorySize, SMEM);

    float* tx = nullptr; float* ha = nullptr; float* hb = nullptr;
    cudaGetSymbolAddress((void**)&tx, g_tx);
    cudaGetSymbolAddress((void**)&ha, g_ha);
    cudaGetSymbolAddress((void**)&hb, g_hb);

    zero_kernel<<<NN / 256, 256>>>();                       // 0
    deg_kernel<<<NE / 256, 256>>>(ei);                      // 1
    fill_kernel<<<NE / 256, 256>>>(ei, lam);                // 2

    spmv_kernel<128><<<dim3(16, NG), 1024, SMEM>>>(x, lam, tx);   // 3 <- ncu captures this
    gemm_kernel<640, 32, 512><<<NN / 512, 256>>>(tx, W1, b1, ha);

    spmv_kernel<32><<<dim3(4, NG), 1024, SMEM>>>(ha, lam, tx);
    gemm_kernel<160, 64, 256><<<NN / 256, 256>>>(tx, W2, b2, hb);

    spmv_kernel<64><<<dim3(8, NG), 1024, SMEM>>>(hb, lam, tx);
    gemm_kernel<320, 64, 256><<<NN / 256, 256>>>(tx, W3, b3, ha);

    pool_fc_kernel<<<NG, 256>>>(ha, fcW1, fcb1, fcW2, fcb2, out);
}